// round 16
// baseline (speedup 1.0000x reference)
#include <cuda_runtime.h>
#include <cuda_bf16.h>
#include <cstdint>
#include <math.h>

#define N_NODES 100000
#define N_EDGES 1600000
#define HID 128
#define OUTD 4
#define N_EXP 4
#define NUM_GRAPHS 64
#define PRIOR_W 0.35f
#define SCAN_BLOCKS ((N_NODES + 255) / 256)
#define NH ((size_t)N_NODES * HID)
#define NCHUNK 4
#define CHROWS 25000

// ---------------- scratch (fp32) ----------------
__device__ __align__(16) float g_U[(size_t)N_NODES * 16];   // [node][e*4+j]
__device__ __align__(16) float g_R[(size_t)N_NODES * 16];
__device__ __align__(16) float g_RT[N_NODES * 4];           // router logits
__device__ __align__(16) float g_GW[N_NODES * N_EXP];
__device__ __align__(16) float g_C[NUM_GRAPHS * HID];
__device__ float g_NCNT[NUM_GRAPHS], g_ECNT[NUM_GRAPHS], g_SF[NUM_GRAPHS * 3], g_LNN[NUM_GRAPHS];
// ---------------- scratch (split bf16) ----------------
__device__ __align__(16) __nv_bfloat16 g_Hh[NH],   g_Hl[NH];
__device__ __align__(16) __nv_bfloat16 g_AGHh[NH], g_AGHl[NH];
__device__ __align__(16) __nv_bfloat16 g_Z1h[N_EXP * NH],  g_Z1l[N_EXP * NH];
__device__ __align__(16) __nv_bfloat16 g_AGZh[N_EXP * NH], g_AGZl[N_EXP * NH];
// 18 weight mats: [0..3]=start_rel, [4..7]=start_root, [8..11]=mid_rel, [12..15]=mid_root,
// [16]=encW2, [17]=rtW1[:128]
#define NMATS 18
__device__ __align__(16) __nv_bfloat16 g_Wh[NMATS * HID * HID], g_Wl[NMATS * HID * HID];
// ---------------- scratch (CSR) ----------------
__device__ int g_cnt[N_NODES], g_cnt2[N_NODES], g_rs[N_NODES], g_bsum[512];
__device__ int g_csr[N_EDGES];

// ================= helpers =================
__device__ __forceinline__ unsigned smem_u32(const void* p) {
    return (unsigned)__cvta_generic_to_shared(p);
}
__device__ __forceinline__ void cp16(unsigned d, const void* s, int sz) {
    asm volatile("cp.async.cg.shared.global [%0], [%1], 16, %2;"
                 :: "r"(d), "l"(s), "r"(sz));
}
__device__ __forceinline__ void cp_commit() { asm volatile("cp.async.commit_group;"); }
__device__ __forceinline__ void cp_wait1()  { asm volatile("cp.async.wait_group 1;"); }
__device__ __forceinline__ void ldsm_x4(unsigned a, unsigned& r0, unsigned& r1,
                                        unsigned& r2, unsigned& r3) {
    asm volatile("ldmatrix.sync.aligned.m8n8.x4.shared.b16 {%0,%1,%2,%3}, [%4];"
                 : "=r"(r0), "=r"(r1), "=r"(r2), "=r"(r3) : "r"(a));
}
__device__ __forceinline__ void ldsm_x4_t(unsigned a, unsigned& r0, unsigned& r1,
                                          unsigned& r2, unsigned& r3) {
    asm volatile("ldmatrix.sync.aligned.m8n8.x4.trans.shared.b16 {%0,%1,%2,%3}, [%4];"
                 : "=r"(r0), "=r"(r1), "=r"(r2), "=r"(r3) : "r"(a));
}
__device__ __forceinline__ void mma_bf16(float* c, const unsigned* a,
                                         unsigned b0, unsigned b1) {
    asm volatile("mma.sync.aligned.m16n8k16.row.col.f32.bf16.bf16.f32 "
                 "{%0,%1,%2,%3}, {%4,%5,%6,%7}, {%8,%9}, {%0,%1,%2,%3};"
                 : "+f"(c[0]), "+f"(c[1]), "+f"(c[2]), "+f"(c[3])
                 : "r"(a[0]), "r"(a[1]), "r"(a[2]), "r"(a[3]), "r"(b0), "r"(b1));
}
__device__ __forceinline__ void split_bf16(float v, __nv_bfloat16& h, __nv_bfloat16& l) {
    h = __float2bfloat16_rn(v);
    l = __float2bfloat16_rn(v - __bfloat162float(h));
}
__device__ __forceinline__ unsigned pack2(__nv_bfloat16 a, __nv_bfloat16 b) {
    __nv_bfloat162 p; p.x = a; p.y = b;
    return *(unsigned*)&p;
}

// ======== fused GEMM: hi/lo bf16 in, 3xMMA split accumulation ========
// rows processed: [rowBase + blockIdx.x*128, rowLimit)
#define APAD 24
#define WPAD 136

__global__ __launch_bounds__(256) void k_gemm2(
    const __nv_bfloat16* __restrict__ Ahi, const __nv_bfloat16* __restrict__ Alo,
    const __nv_bfloat16* __restrict__ Bhi, const __nv_bfloat16* __restrict__ Blo,
    const __nv_bfloat16* __restrict__ Wrel_h, const __nv_bfloat16* __restrict__ Wrel_l,
    const __nv_bfloat16* __restrict__ Wroot_h, const __nv_bfloat16* __restrict__ Wroot_l,
    const float* __restrict__ bias,
    __nv_bfloat16* __restrict__ outh, __nv_bfloat16* __restrict__ outl,
    const float* __restrict__ eW, const float* __restrict__ erW,
    float* __restrict__ U, float* __restrict__ R,
    const float* __restrict__ rowTab, const int* __restrict__ batchIdx,
    size_t inStride, size_t outStride, size_t wStride, size_t biasStride,
    size_t projStride, int uStride,
    int do_relu, int nsteps, int rowBase, int rowLimit)
{
    __shared__ __nv_bfloat16 Ah[2][128][APAD], Al[2][128][APAD];
    __shared__ __nv_bfloat16 Wh[2][16][WPAD],  Wl[2][16][WPAD];

    int ex = blockIdx.y;
    Ahi += (size_t)ex * inStride;  Alo += (size_t)ex * inStride;
    if (Bhi) { Bhi += (size_t)ex * inStride; Blo += (size_t)ex * inStride; }
    Wrel_h += (size_t)ex * wStride;  Wrel_l += (size_t)ex * wStride;
    if (Wroot_h) { Wroot_h += (size_t)ex * wStride; Wroot_l += (size_t)ex * wStride; }
    bias += (size_t)ex * biasStride;
    if (outh) { outh += (size_t)ex * outStride; outl += (size_t)ex * outStride; }
    bool project = (eW != nullptr);
    bool projR = (erW != nullptr);
    if (project) {
        eW += (size_t)ex * projStride;
        U += (size_t)ex * 4;
        if (projR) { erW += (size_t)ex * projStride; R += (size_t)ex * 4; }
    }

    int tid = threadIdx.x;
    int lane = tid & 31, wid = tid >> 5;
    int wm = wid & 3, wn = wid >> 2;
    int row0 = rowBase + blockIdx.x * 128;

    float acc[2][8][4];
    #pragma unroll
    for (int i = 0; i < 2; ++i)
        #pragma unroll
        for (int j = 0; j < 8; ++j)
            #pragma unroll
            for (int k = 0; k < 4; ++k) acc[i][j][k] = 0.f;

    int ar = tid >> 1, ac = (tid & 1) * 8;
    int wk = tid >> 4, wc = (tid & 15) * 8;

    auto prefetch = [&](int kt, int st) {
        const __nv_bfloat16* Ah_src = (kt < 8) ? Ahi : Bhi;
        const __nv_bfloat16* Al_src = (kt < 8) ? Alo : Blo;
        const __nv_bfloat16* Wh_src = (kt < 8) ? Wrel_h : Wroot_h;
        const __nv_bfloat16* Wl_src = (kt < 8) ? Wrel_l : Wroot_l;
        int kk0 = (kt & 7) * 16;
        int gr = row0 + ar;
        int sz = (gr < rowLimit) ? 16 : 0;
        int grc = (gr < rowLimit) ? gr : rowBase;
        size_t aoff = (size_t)grc * HID + kk0 + ac;
        cp16(smem_u32(&Ah[st][ar][ac]), Ah_src + aoff, sz);
        cp16(smem_u32(&Al[st][ar][ac]), Al_src + aoff, sz);
        size_t woff = (size_t)(kk0 + wk) * HID + wc;
        cp16(smem_u32(&Wh[st][wk][wc]), Wh_src + woff, 16);
        cp16(smem_u32(&Wl[st][wk][wc]), Wl_src + woff, 16);
    };

    prefetch(0, 0);
    cp_commit();

    int a_row = (lane & 15);
    int a_col = (lane >> 4) * 8;
    int b_krow = (lane & 7) + ((lane >> 3) & 1) * 8;
    int b_ncol = (lane >> 4) * 8;

    for (int kt = 0; kt < nsteps; ++kt) {
        int st = kt & 1;
        if (kt + 1 < nsteps) prefetch(kt + 1, st ^ 1);
        cp_commit();
        cp_wait1();
        __syncthreads();

        unsigned ah[2][4], al[2][4];
        #pragma unroll
        for (int mf = 0; mf < 2; ++mf) {
            int r = wm * 32 + mf * 16 + a_row;
            ldsm_x4(smem_u32(&Ah[st][r][a_col]), ah[mf][0], ah[mf][1], ah[mf][2], ah[mf][3]);
            ldsm_x4(smem_u32(&Al[st][r][a_col]), al[mf][0], al[mf][1], al[mf][2], al[mf][3]);
        }
        unsigned bh[8][2], bl[8][2];
        #pragma unroll
        for (int p = 0; p < 4; ++p) {
            int nb = wn * 64 + p * 16 + b_ncol;
            ldsm_x4_t(smem_u32(&Wh[st][b_krow][nb]),
                      bh[2*p][0], bh[2*p][1], bh[2*p+1][0], bh[2*p+1][1]);
            ldsm_x4_t(smem_u32(&Wl[st][b_krow][nb]),
                      bl[2*p][0], bl[2*p][1], bl[2*p+1][0], bl[2*p+1][1]);
        }
        #pragma unroll
        for (int mf = 0; mf < 2; ++mf)
            #pragma unroll
            for (int nf = 0; nf < 8; ++nf) {
                mma_bf16(acc[mf][nf], ah[mf], bh[nf][0], bh[nf][1]);
                mma_bf16(acc[mf][nf], ah[mf], bl[nf][0], bl[nf][1]);
                mma_bf16(acc[mf][nf], al[mf], bh[nf][0], bh[nf][1]);
            }
        __syncthreads();
    }

    float (*eWs)[4]  = (float(*)[4])((char*)&Ah[0][0][0]);
    float (*erWs)[4] = (float(*)[4])((char*)&Ah[0][0][0] + 2048);
    float (*uacc)[8] = (float(*)[8])((char*)&Ah[0][0][0] + 4096);
    if (project) {
        for (int i = tid; i < 512; i += 256) {
            ((float*)eWs)[i] = eW[i];
            if (projR) ((float*)erWs)[i] = erW[i];
        }
        for (int i = tid; i < 128 * 8; i += 256) ((float*)uacc)[i] = 0.f;
        __syncthreads();
    }

    float up[2][2][4], rp[2][2][4];
    if (project) {
        #pragma unroll
        for (int a = 0; a < 2; ++a)
            #pragma unroll
            for (int b = 0; b < 2; ++b)
                #pragma unroll
                for (int j = 0; j < 4; ++j) { up[a][b][j] = 0.f; rp[a][b][j] = 0.f; }
    }

    #pragma unroll
    for (int mf = 0; mf < 2; ++mf) {
        int rbase = wm * 32 + mf * 16 + (lane >> 2);
        int g0r = row0 + rbase, g1r = g0r + 8;
        const float* tab0 = nullptr;
        const float* tab1 = nullptr;
        if (rowTab) {
            tab0 = rowTab + (size_t)((g0r < rowLimit) ? batchIdx[g0r] : 0) * HID;
            tab1 = rowTab + (size_t)((g1r < rowLimit) ? batchIdx[g1r] : 0) * HID;
        }
        #pragma unroll
        for (int nf = 0; nf < 8; ++nf) {
            int c = wn * 64 + nf * 8 + (lane & 3) * 2;
            float b0 = __ldg(&bias[c]), b1 = __ldg(&bias[c + 1]);
            float o0 = acc[mf][nf][0] + b0, o1 = acc[mf][nf][1] + b1;
            float o2 = acc[mf][nf][2] + b0, o3 = acc[mf][nf][3] + b1;
            if (rowTab) {
                o0 += tab0[c]; o1 += tab0[c + 1];
                o2 += tab1[c]; o3 += tab1[c + 1];
            }
            if (do_relu) {
                o0 = fmaxf(o0, 0.f); o1 = fmaxf(o1, 0.f);
                o2 = fmaxf(o2, 0.f); o3 = fmaxf(o3, 0.f);
            }
            if (outh) {
                if (g0r < rowLimit) {
                    __nv_bfloat16 h0, l0, h1, l1;
                    split_bf16(o0, h0, l0); split_bf16(o1, h1, l1);
                    *(unsigned*)&outh[(size_t)g0r * HID + c] = pack2(h0, h1);
                    *(unsigned*)&outl[(size_t)g0r * HID + c] = pack2(l0, l1);
                }
                if (g1r < rowLimit) {
                    __nv_bfloat16 h2, l2, h3, l3;
                    split_bf16(o2, h2, l2); split_bf16(o3, h3, l3);
                    *(unsigned*)&outh[(size_t)g1r * HID + c] = pack2(h2, h3);
                    *(unsigned*)&outl[(size_t)g1r * HID + c] = pack2(l2, l3);
                }
            }
            if (project) {
                #pragma unroll
                for (int j = 0; j < 4; ++j) {
                    up[mf][0][j] += o0 * eWs[c][j] + o1 * eWs[c + 1][j];
                    up[mf][1][j] += o2 * eWs[c][j] + o3 * eWs[c + 1][j];
                    if (projR) {
                        rp[mf][0][j] += o0 * erWs[c][j] + o1 * erWs[c + 1][j];
                        rp[mf][1][j] += o2 * erWs[c][j] + o3 * erWs[c + 1][j];
                    }
                }
            }
        }
    }

    if (project) {
        #pragma unroll
        for (int a = 0; a < 2; ++a)
            #pragma unroll
            for (int b = 0; b < 2; ++b)
                #pragma unroll
                for (int j = 0; j < 4; ++j) {
                    up[a][b][j] += __shfl_xor_sync(0xffffffffu, up[a][b][j], 1);
                    up[a][b][j] += __shfl_xor_sync(0xffffffffu, up[a][b][j], 2);
                    if (projR) {
                        rp[a][b][j] += __shfl_xor_sync(0xffffffffu, rp[a][b][j], 1);
                        rp[a][b][j] += __shfl_xor_sync(0xffffffffu, rp[a][b][j], 2);
                    }
                }
        if ((lane & 3) == 0) {
            #pragma unroll
            for (int a = 0; a < 2; ++a)
                #pragma unroll
                for (int b = 0; b < 2; ++b) {
                    int r = wm * 32 + a * 16 + b * 8 + (lane >> 2);
                    #pragma unroll
                    for (int j = 0; j < 4; ++j) {
                        atomicAdd(&uacc[r][j], up[a][b][j]);
                        if (projR) atomicAdd(&uacc[r][4 + j], rp[a][b][j]);
                    }
                }
        }
        __syncthreads();
        if (tid < 128) {
            int g = row0 + tid;
            if (g < rowLimit) {
                *(float4*)&U[(size_t)g * uStride] = make_float4(uacc[tid][0], uacc[tid][1],
                                                                uacc[tid][2], uacc[tid][3]);
                if (projR)
                    *(float4*)&R[(size_t)g * uStride] = make_float4(uacc[tid][4], uacc[tid][5],
                                                                    uacc[tid][6], uacc[tid][7]);
            }
        }
    }
}

// ---------------- weight pre-split (mat range [m0,m1)) ----------------
__global__ void k_convw(const float* __restrict__ sRelW, const float* __restrict__ sRootW,
                        const float* __restrict__ mRelW, const float* __restrict__ mRootW,
                        const float* __restrict__ encW2, const float* __restrict__ rtW1,
                        __nv_bfloat16* __restrict__ wh, __nv_bfloat16* __restrict__ wl,
                        int m0, int m1) {
    int i = blockIdx.x * blockDim.x + threadIdx.x;
    int n = (m1 - m0) * HID * HID;
    if (i >= n) return;
    int mat = m0 + i / (HID * HID), off = i % (HID * HID);
    float v;
    if (mat == 16) v = encW2[off];
    else if (mat == 17) v = rtW1[off];
    else {
        const float* srcs[4] = {sRelW, sRootW, mRelW, mRootW};
        v = srcs[mat >> 2][(size_t)(mat & 3) * HID * HID + off];
    }
    __nv_bfloat16 h, l;
    split_bf16(v, h, l);
    wh[(size_t)mat * HID * HID + off] = h;
    wl[(size_t)mat * HID * HID + off] = l;
}

// ---------------- encoder layer 1 ----------------
__global__ void k_enc1(const float* __restrict__ x,
                       const float* __restrict__ W1, const float* __restrict__ b1,
                       __nv_bfloat16* __restrict__ oh, __nv_bfloat16* __restrict__ ol) {
    __shared__ float xs[8][8];
    int n0 = blockIdx.x * 8;
    int t = threadIdx.x;
    if (t < 48) {
        int j = t / 6, f = t % 6;
        int node = n0 + j;
        xs[j][f] = (node < N_NODES) ? x[(size_t)node * 16 + 4 + f] : 0.f;
    }
    __syncthreads();
    float bb1 = b1[t];
    float w[6];
    #pragma unroll
    for (int f = 0; f < 6; ++f) w[f] = __ldg(&W1[f * HID + t]);
    #pragma unroll
    for (int j = 0; j < 8; ++j) {
        int node = n0 + j;
        if (node >= N_NODES) break;
        float acc = bb1;
        #pragma unroll
        for (int f = 0; f < 6; ++f) acc += xs[j][f] * w[f];
        acc = fmaxf(acc, 0.f);
        __nv_bfloat16 hi, lo;
        split_bf16(acc, hi, lo);
        oh[(size_t)node * HID + t] = hi;
        ol[(size_t)node * HID + t] = lo;
    }
}

// ---------------- CSR build ----------------
__global__ void k_count(const int* __restrict__ dst, int* __restrict__ cnt) {
    int e = blockIdx.x * blockDim.x + threadIdx.x;
    if (e < N_EDGES) atomicAdd(&cnt[dst[e]], 1);
}
__global__ void k_scan1(const int* __restrict__ cnt, int* __restrict__ rs,
                        int* __restrict__ bsum) {
    __shared__ int s[256];
    int i = blockIdx.x * 256 + threadIdx.x;
    int v = (i < N_NODES) ? cnt[i] : 0;
    s[threadIdx.x] = v;
    __syncthreads();
    #pragma unroll
    for (int o = 1; o < 256; o <<= 1) {
        int t = (threadIdx.x >= o) ? s[threadIdx.x - o] : 0;
        __syncthreads();
        s[threadIdx.x] += t;
        __syncthreads();
    }
    if (i < N_NODES) rs[i] = s[threadIdx.x] - v;
    if (threadIdx.x == 255) bsum[blockIdx.x] = s[255];
}
__global__ void k_scan2(int* __restrict__ bsum) {
    __shared__ int s[512];
    int v = (threadIdx.x < SCAN_BLOCKS) ? bsum[threadIdx.x] : 0;
    s[threadIdx.x] = v;
    __syncthreads();
    #pragma unroll
    for (int o = 1; o < 512; o <<= 1) {
        int t = (threadIdx.x >= o) ? s[threadIdx.x - o] : 0;
        __syncthreads();
        s[threadIdx.x] += t;
        __syncthreads();
    }
    if (threadIdx.x < SCAN_BLOCKS) bsum[threadIdx.x] = s[threadIdx.x] - v;
}
__global__ void k_scan3(int* __restrict__ rs, const int* __restrict__ bsum) {
    int i = blockIdx.x * 256 + threadIdx.x;
    if (i < N_NODES) rs[i] += bsum[blockIdx.x];
}
__global__ void k_place(const int* __restrict__ src, const int* __restrict__ dst,
                        const int* __restrict__ rs, int* __restrict__ cnt2,
                        int* __restrict__ csr) {
    int e = blockIdx.x * blockDim.x + threadIdx.x;
    if (e >= N_EDGES) return;
    int d = dst[e];
    int pos = rs[d] + atomicAdd(&cnt2[d], 1);
    csr[pos] = src[e];
}

// ---------------- CSR gather: hi/lo lane split + 2-edge unroll; node range chunked ----
__global__ void k_gatherb(const __nv_bfloat16* __restrict__ fh,
                          const __nv_bfloat16* __restrict__ fl,
                          const int* __restrict__ rs, const int* __restrict__ cnt,
                          const int* __restrict__ csr,
                          __nv_bfloat16* __restrict__ oh, __nv_bfloat16* __restrict__ ol,
                          size_t exStride, int nodeBase, int nodeLimit) {
    size_t off0 = (size_t)blockIdx.y * exStride;
    fh += off0; fl += off0; oh += off0; ol += off0;
    int node = nodeBase + ((blockIdx.x * blockDim.x + threadIdx.x) >> 5);
    int lane = threadIdx.x & 31;
    if (node >= nodeLimit) return;
    int start = rs[node], deg = cnt[node];
    const __nv_bfloat16* base = (lane < 16) ? fh : fl;
    int c8 = (lane & 15) * 8;
    float a[8] = {0.f, 0.f, 0.f, 0.f, 0.f, 0.f, 0.f, 0.f};
    int e = 0;
    for (; e + 1 < deg; e += 2) {
        int sid0 = __ldg(&csr[start + e]);
        int sid1 = __ldg(&csr[start + e + 1]);
        uint4 v0 = *(const uint4*)&base[(size_t)sid0 * HID + c8];
        uint4 v1 = *(const uint4*)&base[(size_t)sid1 * HID + c8];
        const __nv_bfloat162* p0 = (const __nv_bfloat162*)&v0;
        const __nv_bfloat162* p1 = (const __nv_bfloat162*)&v1;
        #pragma unroll
        for (int q = 0; q < 4; ++q) {
            a[2 * q]     += __bfloat162float(p0[q].x);
            a[2 * q + 1] += __bfloat162float(p0[q].y);
        }
        #pragma unroll
        for (int q = 0; q < 4; ++q) {
            a[2 * q]     += __bfloat162float(p1[q].x);
            a[2 * q + 1] += __bfloat162float(p1[q].y);
        }
    }
    if (e < deg) {
        int sid = __ldg(&csr[start + e]);
        uint4 v = *(const uint4*)&base[(size_t)sid * HID + c8];
        const __nv_bfloat162* pp = (const __nv_bfloat162*)&v;
        #pragma unroll
        for (int q = 0; q < 4; ++q) {
            a[2 * q]     += __bfloat162float(pp[q].x);
            a[2 * q + 1] += __bfloat162float(pp[q].y);
        }
    }
    #pragma unroll
    for (int q = 0; q < 8; ++q)
        a[q] += __shfl_down_sync(0xffffffffu, a[q], 16);
    if (lane < 16) {
        unsigned hs[4], ls[4];
        #pragma unroll
        for (int q = 0; q < 4; ++q) {
            __nv_bfloat16 h0, l0, h1, l1;
            split_bf16(a[2 * q], h0, l0);
            split_bf16(a[2 * q + 1], h1, l1);
            hs[q] = pack2(h0, h1);
            ls[q] = pack2(l0, l1);
        }
        size_t o = (size_t)node * HID + c8;
        *(uint4*)&oh[o] = make_uint4(hs[0], hs[1], hs[2], hs[3]);
        *(uint4*)&ol[o] = make_uint4(ls[0], ls[1], ls[2], ls[3]);
    }
}

// ---------------- graph stats ----------------
__global__ void k_node_count(const int* __restrict__ batch, float* __restrict__ ncnt) {
    int g = threadIdx.x;
    if (g >= NUM_GRAPHS) return;
    int lo = 0, hi = N_NODES;
    while (lo < hi) { int m = (lo + hi) >> 1; if (batch[m] < g) lo = m + 1; else hi = m; }
    int a = lo;
    lo = 0; hi = N_NODES;
    while (lo < hi) { int m = (lo + hi) >> 1; if (batch[m] < g + 1) lo = m + 1; else hi = m; }
    ncnt[g] = (float)(lo - a);
}
__global__ void k_edge_count(const int* __restrict__ src, const int* __restrict__ batch,
                             float* __restrict__ ecnt) {
    __shared__ float sc[NUM_GRAPHS];
    int t = threadIdx.x;
    if (t < NUM_GRAPHS) sc[t] = 0.f;
    __syncthreads();
    for (int e = blockIdx.x * blockDim.x + t; e < N_EDGES; e += gridDim.x * blockDim.x)
        atomicAdd(&sc[batch[src[e]]], 1.f);
    __syncthreads();
    if (t < NUM_GRAPHS) atomicAdd(&ecnt[t], sc[t]);
}
__global__ void k_stats(const float* __restrict__ ncnt, const float* __restrict__ ecnt,
                        float* __restrict__ sf, float* __restrict__ lnn) {
    __shared__ float nn[64], ee[64], dd[64], ll[64];
    __shared__ float mean[3], istd[3], lmin, lrange;
    int g = threadIdx.x;
    float n = fmaxf(ncnt[g], 1.f);
    float e = ecnt[g];
    float d = e / fmaxf(n * (n - 1.f), 1.f);
    float lg = logf(n);
    nn[g] = n; ee[g] = e; dd[g] = d; ll[g] = lg;
    __syncthreads();
    if (g == 0) {
        double s0 = 0, s1 = 0, s2 = 0;
        float mn = ll[0], mx = ll[0];
        for (int i = 0; i < 64; ++i) {
            s0 += nn[i]; s1 += ee[i]; s2 += dd[i];
            mn = fminf(mn, ll[i]); mx = fmaxf(mx, ll[i]);
        }
        double m0 = s0 / 64, m1 = s1 / 64, m2 = s2 / 64;
        double v0 = 0, v1 = 0, v2 = 0;
        for (int i = 0; i < 64; ++i) {
            double a = nn[i] - m0, b = ee[i] - m1, c = dd[i] - m2;
            v0 += a * a; v1 += b * b; v2 += c * c;
        }
        mean[0] = (float)m0; mean[1] = (float)m1; mean[2] = (float)m2;
        istd[0] = 1.f / ((float)sqrt(v0 / 64) + 1e-6f);
        istd[1] = 1.f / ((float)sqrt(v1 / 64) + 1e-6f);
        istd[2] = 1.f / ((float)sqrt(v2 / 64) + 1e-6f);
        lmin = mn; lrange = mx - mn + 1e-6f;
    }
    __syncthreads();
    sf[g * 3 + 0] = (nn[g] - mean[0]) * istd[0];
    sf[g * 3 + 1] = (ee[g] - mean[1]) * istd[1];
    sf[g * 3 + 2] = (dd[g] - mean[2]) * istd[2];
    lnn[g] = (ll[g] - lmin) / lrange;
}
__global__ void k_sfproj(const float* __restrict__ sf, const float* __restrict__ rtW1,
                         float* __restrict__ C) {
    int g = blockIdx.x, c = threadIdx.x;
    C[g * HID + c] = sf[g * 3 + 0] * rtW1[128 * HID + c]
                   + sf[g * 3 + 1] * rtW1[129 * HID + c]
                   + sf[g * 3 + 2] * rtW1[130 * HID + c];
}

// ---------------- gating ----------------
__global__ void k_gating(const float* __restrict__ logits, const int* __restrict__ batch,
                         const float* __restrict__ lnn, const float* __restrict__ centers,
                         const float* __restrict__ b2, float* __restrict__ w) {
    int i = blockIdx.x * blockDim.x + threadIdx.x;
    if (i >= N_NODES) return;
    float4 lg = *(const float4*)&logits[(size_t)i * 4];
    float ln = lnn[batch[i]];
    float l[4];
    float c0 = centers[0], c1 = centers[1], c2 = centers[2], c3 = centers[3];
    float d0 = ln - c0, d1 = ln - c1, d2 = ln - c2, d3 = ln - c3;
    l[0] = (1.f - PRIOR_W) * (lg.x + b2[0]) - PRIOR_W * d0 * d0;
    l[1] = (1.f - PRIOR_W) * (lg.y + b2[1]) - PRIOR_W * d1 * d1;
    l[2] = (1.f - PRIOR_W) * (lg.z + b2[2]) - PRIOR_W * d2 * d2;
    l[3] = (1.f - PRIOR_W) * (lg.w + b2[3]) - PRIOR_W * d3 * d3;
    float m = fmaxf(fmaxf(l[0], l[1]), fmaxf(l[2], l[3]));
    float p[4], s = 0.f;
    #pragma unroll
    for (int k = 0; k < 4; ++k) { p[k] = expf(l[k] - m); s += p[k]; }
    #pragma unroll
    for (int k = 0; k < 4; ++k) p[k] /= s;
    int i1 = 0;
    for (int k = 1; k < 4; ++k) if (p[k] > p[i1]) i1 = k;
    int i2 = -1;
    for (int k = 0; k < 4; ++k) { if (k == i1) continue; if (i2 < 0 || p[k] > p[i2]) i2 = k; }
    float inv = 1.f / (p[i1] + p[i2] + 1e-8f);
    float ww[4] = {0.f, 0.f, 0.f, 0.f};
    ww[i1] = p[i1] * inv; ww[i2] = p[i2] * inv;
    *(float4*)&w[(size_t)i * 4] = make_float4(ww[0], ww[1], ww[2], ww[3]);
}

// ---------------- fused finale ----------------
__global__ void k_final_all(const float* __restrict__ U, const float* __restrict__ R,
                            const float* __restrict__ eRelB, const float* __restrict__ w,
                            const int* __restrict__ rs, const int* __restrict__ cnt,
                            const int* __restrict__ csr, float* __restrict__ out) {
    int node = (blockIdx.x * blockDim.x + threadIdx.x) >> 5;
    int lane = threadIdx.x & 31;
    if (node >= N_NODES) return;
    int start = rs[node], deg = cnt[node];
    int comp = lane & 15;
    float acc = 0.f;
    for (int e2 = lane >> 4; e2 < deg; e2 += 2) {
        int sid = __ldg(&csr[start + e2]);
        acc += U[(size_t)sid * 16 + comp];
    }
    acc += __shfl_down_sync(0xffffffffu, acc, 16);
    float val = 0.f;
    if (lane < 16) {
        int e = comp >> 2;
        val = (acc + __ldg(&eRelB[comp]) + R[(size_t)node * 16 + comp])
              * w[(size_t)node * 4 + e];
    }
    val += __shfl_down_sync(0xffffffffu, val, 8);
    val += __shfl_down_sync(0xffffffffu, val, 4);
    if (lane < 4) out[(size_t)node * 4 + lane] = val;
}

// ---------------- host ----------------
extern "C" void kernel_launch(void* const* d_in, const int* in_sizes, int n_in,
                              void* d_out, int out_size) {
    const float* x       = (const float*)d_in[0];
    const int*   ei      = (const int*)d_in[1];
    const int*   src     = ei;
    const int*   dst     = ei + N_EDGES;
    const int*   batch   = (const int*)d_in[2];
    const float* encW1   = (const float*)d_in[3];
    const float* encb1   = (const float*)d_in[4];
    const float* encW2   = (const float*)d_in[5];
    const float* encb2   = (const float*)d_in[6];
    const float* rtW1    = (const float*)d_in[7];
    const float* rtb1    = (const float*)d_in[8];
    const float* rtW2    = (const float*)d_in[9];
    const float* rtb2    = (const float*)d_in[10];
    const float* centers = (const float*)d_in[11];
    const float* sRelW   = (const float*)d_in[12];
    const float* sRelB   = (const float*)d_in[13];
    const float* sRootW  = (const float*)d_in[14];
    const float* mRelW   = (const float*)d_in[15];
    const float* mRelB   = (const float*)d_in[16];
    const float* mRootW  = (const float*)d_in[17];
    const float* eRelW   = (const float*)d_in[18];
    const float* eRelB   = (const float*)d_in[19];
    const float* eRootW  = (const float*)d_in[20];
    float* out = (float*)d_out;

    void* p;
    cudaGetSymbolAddress(&p, g_U);    float* U    = (float*)p;
    cudaGetSymbolAddress(&p, g_R);    float* R    = (float*)p;
    cudaGetSymbolAddress(&p, g_RT);   float* RT   = (float*)p;
    cudaGetSymbolAddress(&p, g_GW);   float* GW   = (float*)p;
    cudaGetSymbolAddress(&p, g_C);    float* C    = (float*)p;
    cudaGetSymbolAddress(&p, g_NCNT); float* NCNT = (float*)p;
    cudaGetSymbolAddress(&p, g_ECNT); float* ECNT = (float*)p;
    cudaGetSymbolAddress(&p, g_SF);   float* SF   = (float*)p;
    cudaGetSymbolAddress(&p, g_LNN);  float* LNN  = (float*)p;
    cudaGetSymbolAddress(&p, g_Hh);   __nv_bfloat16* Hh   = (__nv_bfloat16*)p;
    cudaGetSymbolAddress(&p, g_Hl);   __nv_bfloat16* Hl   = (__nv_bfloat16*)p;
    cudaGetSymbolAddress(&p, g_Z1h);  __nv_bfloat16* Z1h  = (__nv_bfloat16*)p;
    cudaGetSymbolAddress(&p, g_Z1l);  __nv_bfloat16* Z1l  = (__nv_bfloat16*)p;
    cudaGetSymbolAddress(&p, g_AGHh); __nv_bfloat16* AGHh = (__nv_bfloat16*)p;
    cudaGetSymbolAddress(&p, g_AGHl); __nv_bfloat16* AGHl = (__nv_bfloat16*)p;
    cudaGetSymbolAddress(&p, g_AGZh); __nv_bfloat16* AGZh = (__nv_bfloat16*)p;
    cudaGetSymbolAddress(&p, g_AGZl); __nv_bfloat16* AGZl = (__nv_bfloat16*)p;
    cudaGetSymbolAddress(&p, g_Wh);   __nv_bfloat16* Wh   = (__nv_bfloat16*)p;
    cudaGetSymbolAddress(&p, g_Wl);   __nv_bfloat16* Wl   = (__nv_bfloat16*)p;
    cudaGetSymbolAddress(&p, g_cnt);  int* CNT  = (int*)p;
    cudaGetSymbolAddress(&p, g_cnt2); int* CNT2 = (int*)p;
    cudaGetSymbolAddress(&p, g_rs);   int* RS   = (int*)p;
    cudaGetSymbolAddress(&p, g_bsum); int* BSUM = (int*)p;
    cudaGetSymbolAddress(&p, g_csr);  int* CSR  = (int*)p;

    const size_t MS = (size_t)HID * HID;
    int gemm_blocks = (N_NODES + 127) / 128;
    int gather_blocks = (N_NODES * 32 + 255) / 256;
    int chunk_gemm_blocks = (CHROWS + 127) / 128;
    int chunk_gather_blocks = (CHROWS * 32 + 255) / 256;

    cudaStream_t s[N_EXP];
    for (int i = 0; i < N_EXP; ++i) cudaStreamCreateWithFlags(&s[i], cudaStreamNonBlocking);
    cudaEvent_t evRoot, evCSR, evH, evGW, evWB, evAGHc[NCHUNK], evE[N_EXP];
    cudaEventCreateWithFlags(&evRoot, cudaEventDisableTiming);
    cudaEventCreateWithFlags(&evCSR, cudaEventDisableTiming);
    cudaEventCreateWithFlags(&evH, cudaEventDisableTiming);
    cudaEventCreateWithFlags(&evGW, cudaEventDisableTiming);
    cudaEventCreateWithFlags(&evWB, cudaEventDisableTiming);
    for (int i = 0; i < NCHUNK; ++i) cudaEventCreateWithFlags(&evAGHc[i], cudaEventDisableTiming);
    for (int i = 0; i < N_EXP; ++i) cudaEventCreateWithFlags(&evE[i], cudaEventDisableTiming);

    cudaEventRecord(evRoot, 0);

    // ---- side stream s[0]: CSR build ----
    cudaStreamWaitEvent(s[0], evRoot, 0);
    cudaMemsetAsync(CNT, 0, N_NODES * sizeof(int), s[0]);
    cudaMemsetAsync(CNT2, 0, N_NODES * sizeof(int), s[0]);
    k_count<<<(N_EDGES + 255) / 256, 256, 0, s[0]>>>(dst, CNT);
    k_scan1<<<SCAN_BLOCKS, 256, 0, s[0]>>>(CNT, RS, BSUM);
    k_scan2<<<1, 512, 0, s[0]>>>(BSUM);
    k_scan3<<<SCAN_BLOCKS, 256, 0, s[0]>>>(RS, BSUM);
    k_place<<<(N_EDGES + 255) / 256, 256, 0, s[0]>>>(src, dst, RS, CNT2, CSR);
    cudaEventRecord(evCSR, s[0]);

    // ---- side stream s[1]: stats, later router+gating ----
    cudaStreamWaitEvent(s[1], evRoot, 0);
    k_node_count<<<1, 64, 0, s[1]>>>(batch, NCNT);
    cudaMemsetAsync(ECNT, 0, NUM_GRAPHS * sizeof(float), s[1]);
    k_edge_count<<<1024, 256, 0, s[1]>>>(src, batch, ECNT);
    k_stats<<<1, 64, 0, s[1]>>>(NCNT, ECNT, SF, LNN);
    k_sfproj<<<NUM_GRAPHS, HID, 0, s[1]>>>(SF, rtW1, C);

    // ---- side stream s[2]: expert weight pre-split (mats 0..15) ----
    cudaStreamWaitEvent(s[2], evRoot, 0);
    k_convw<<<(16 * HID * HID + 255) / 256, 256, 0, s[2]>>>(
        sRelW, sRootW, mRelW, mRootW, encW2, rtW1, Wh, Wl, 0, 16);
    cudaEventRecord(evWB, s[2]);

    // ---- default (critical path): enc/router weights, encoder ----
    k_convw<<<(2 * HID * HID + 255) / 256, 256>>>(
        sRelW, sRootW, mRelW, mRootW, encW2, rtW1, Wh, Wl, 16, 18);
    k_enc1<<<(N_NODES + 7) / 8, 128>>>(x, encW1, encb1, Z1h, Z1l);  // reuse Z1[0] as h1
    k_gemm2<<<gemm_blocks, 256>>>(Z1h, Z1l, nullptr, nullptr,
        Wh + 16 * MS, Wl + 16 * MS, nullptr, nullptr,
        encb2, Hh, Hl, nullptr, nullptr, nullptr, nullptr, nullptr, nullptr,
        0, 0, 0, 0, 0, 4, 0, 8, 0, N_NODES);
    cudaEventRecord(evH, 0);

    // router+gating on s[1] (dedicated RT buffer, fully off critical path)
    cudaStreamWaitEvent(s[1], evH, 0);
    k_gemm2<<<gemm_blocks, 256, 0, s[1]>>>(Hh, Hl, nullptr, nullptr,
        Wh + 17 * MS, Wl + 17 * MS, nullptr, nullptr,
        rtb1, nullptr, nullptr, rtW2, nullptr, RT, nullptr, C, batch,
        0, 0, 0, 0, 0, 4, 1, 8, 0, N_NODES);
    k_gating<<<(N_NODES + 255) / 256, 256, 0, s[1]>>>(RT, batch, LNN, centers, rtb2, GW);
    cudaEventRecord(evGW, s[1]);

    // ---- default: join CSR, then CHUNKED shared start aggregation (4 node ranges) ----
    cudaStreamWaitEvent(0, evCSR, 0);
    for (int c = 0; c < NCHUNK; ++c) {
        int nb = c * CHROWS;
        int nl = (c == NCHUNK - 1) ? N_NODES : nb + CHROWS;
        k_gatherb<<<chunk_gather_blocks, 256>>>(Hh, Hl, RS, CNT, CSR, AGHh, AGHl, 0, nb, nl);
        cudaEventRecord(evAGHc[c], 0);
    }

    // ---- per-expert pipelines: start GEMMs chunked against gather chunks ----
    for (int e = 0; e < N_EXP; ++e) {
        cudaStreamWaitEvent(s[e], evWB, 0);
        for (int c = 0; c < NCHUNK; ++c) {
            int rb = c * CHROWS;
            int rl = (c == NCHUNK - 1) ? N_NODES : rb + CHROWS;
            cudaStreamWaitEvent(s[e], evAGHc[c], 0);
            k_gemm2<<<chunk_gemm_blocks, 256, 0, s[e]>>>(AGHh, AGHl, Hh, Hl,
                Wh + (size_t)e * MS, Wl + (size_t)e * MS,
                Wh + (size_t)(4 + e) * MS, Wl + (size_t)(4 + e) * MS,
                sRelB + (size_t)e * HID, Z1h + (size_t)e * NH, Z1l + (size_t)e * NH,
                nullptr, nullptr, nullptr, nullptr, nullptr, nullptr,
                0, 0, 0, 0, 0, 4, 1, 16, rb, rl);
        }
        // mid aggregation (full; needs all Z1 rows of this expert)
        k_gatherb<<<gather_blocks, 256, 0, s[e]>>>(Z1h + (size_t)e * NH, Z1l + (size_t)e * NH,
            RS, CNT, CSR, AGZh + (size_t)e * NH, AGZl + (size_t)e * NH, 0, 0, N_NODES);
        // mid GEMM + fused end projection -> U,R [node][16]
        k_gemm2<<<gemm_blocks, 256, 0, s[e]>>>(AGZh + (size_t)e * NH, AGZl + (size_t)e * NH,
            Z1h + (size_t)e * NH, Z1l + (size_t)e * NH,
            Wh + (size_t)(8 + e) * MS, Wl + (size_t)(8 + e) * MS,
            Wh + (size_t)(12 + e) * MS, Wl + (size_t)(12 + e) * MS,
            mRelB + (size_t)e * HID, nullptr, nullptr,
            eRelW + (size_t)e * HID * OUTD, eRootW + (size_t)e * HID * OUTD,
            U + e * 4, R + e * 4, nullptr, nullptr,
            0, 0, 0, 0, 0, 16, 1, 16, 0, N_NODES);
        cudaEventRecord(evE[e], s[e]);
    }
    for (int e = 0; e < N_EXP; ++e) cudaStreamWaitEvent(0, evE[e], 0);
    cudaStreamWaitEvent(0, evGW, 0);

    // finale on default stream
    k_final_all<<<gather_blocks, 256>>>(U, R, eRelB, GW, RS, CNT, CSR, out);

    for (int i = 0; i < N_EXP; ++i) cudaStreamDestroy(s[i]);
    cudaEventDestroy(evRoot); cudaEventDestroy(evCSR); cudaEventDestroy(evH);
    cudaEventDestroy(evGW); cudaEventDestroy(evWB);
    for (int i = 0; i < NCHUNK; ++i) cudaEventDestroy(evAGHc[i]);
    for (int i = 0; i < N_EXP; ++i) cudaEventDestroy(evE[i]);
}

// round 17
// speedup vs baseline: 1.0241x; 1.0241x over previous
#include <cuda_runtime.h>
#include <cuda_bf16.h>
#include <cstdint>
#include <math.h>

#define N_NODES 100000
#define N_EDGES 1600000
#define HID 128
#define OUTD 4
#define N_EXP 4
#define NUM_GRAPHS 64
#define PRIOR_W 0.35f
#define SCAN_BLOCKS ((N_NODES + 255) / 256)
#define NH ((size_t)N_NODES * HID)

// ---------------- scratch (fp32) ----------------
__device__ __align__(16) float g_U[(size_t)N_NODES * 16];   // [node][e*4+j]
__device__ __align__(16) float g_R[(size_t)N_NODES * 16];
__device__ __align__(16) float g_RT[N_NODES * 4];           // router logits
__device__ __align__(16) float g_GW[N_NODES * N_EXP];
__device__ __align__(16) float g_C[NUM_GRAPHS * HID];
__device__ float g_NCNT[NUM_GRAPHS], g_ECNT[NUM_GRAPHS], g_SF[NUM_GRAPHS * 3], g_LNN[NUM_GRAPHS];
// ---------------- scratch (split bf16) ----------------
__device__ __align__(16) __nv_bfloat16 g_Hh[NH],   g_Hl[NH];
__device__ __align__(16) __nv_bfloat16 g_AGHh[NH], g_AGHl[NH];
__device__ __align__(16) __nv_bfloat16 g_Z1h[N_EXP * NH],  g_Z1l[N_EXP * NH];
__device__ __align__(16) __nv_bfloat16 g_AGZh[N_EXP * NH], g_AGZl[N_EXP * NH];
// 18 weight mats: [0..3]=start_rel, [4..7]=start_root, [8..11]=mid_rel, [12..15]=mid_root,
// [16]=encW2, [17]=rtW1[:128]
#define NMATS 18
__device__ __align__(16) __nv_bfloat16 g_Wh[NMATS * HID * HID], g_Wl[NMATS * HID * HID];
// ---------------- scratch (CSR) ----------------
__device__ int g_cnt[N_NODES], g_cnt2[N_NODES], g_rs[N_NODES], g_bsum[512];
__device__ int g_csr[N_EDGES];

// ================= helpers =================
__device__ __forceinline__ unsigned smem_u32(const void* p) {
    return (unsigned)__cvta_generic_to_shared(p);
}
__device__ __forceinline__ void cp16(unsigned d, const void* s, int sz) {
    asm volatile("cp.async.cg.shared.global [%0], [%1], 16, %2;"
                 :: "r"(d), "l"(s), "r"(sz));
}
__device__ __forceinline__ void cp_commit() { asm volatile("cp.async.commit_group;"); }
__device__ __forceinline__ void cp_wait1()  { asm volatile("cp.async.wait_group 1;"); }
__device__ __forceinline__ void ldsm_x4(unsigned a, unsigned& r0, unsigned& r1,
                                        unsigned& r2, unsigned& r3) {
    asm volatile("ldmatrix.sync.aligned.m8n8.x4.shared.b16 {%0,%1,%2,%3}, [%4];"
                 : "=r"(r0), "=r"(r1), "=r"(r2), "=r"(r3) : "r"(a));
}
__device__ __forceinline__ void ldsm_x4_t(unsigned a, unsigned& r0, unsigned& r1,
                                          unsigned& r2, unsigned& r3) {
    asm volatile("ldmatrix.sync.aligned.m8n8.x4.trans.shared.b16 {%0,%1,%2,%3}, [%4];"
                 : "=r"(r0), "=r"(r1), "=r"(r2), "=r"(r3) : "r"(a));
}
__device__ __forceinline__ void mma_bf16(float* c, const unsigned* a,
                                         unsigned b0, unsigned b1) {
    asm volatile("mma.sync.aligned.m16n8k16.row.col.f32.bf16.bf16.f32 "
                 "{%0,%1,%2,%3}, {%4,%5,%6,%7}, {%8,%9}, {%0,%1,%2,%3};"
                 : "+f"(c[0]), "+f"(c[1]), "+f"(c[2]), "+f"(c[3])
                 : "r"(a[0]), "r"(a[1]), "r"(a[2]), "r"(a[3]), "r"(b0), "r"(b1));
}
__device__ __forceinline__ void split_bf16(float v, __nv_bfloat16& h, __nv_bfloat16& l) {
    h = __float2bfloat16_rn(v);
    l = __float2bfloat16_rn(v - __bfloat162float(h));
}
__device__ __forceinline__ unsigned pack2(__nv_bfloat16 a, __nv_bfloat16 b) {
    __nv_bfloat162 p; p.x = a; p.y = b;
    return *(unsigned*)&p;
}

// ======== fused GEMM: hi/lo bf16 in, 3xMMA split accumulation ========
// __launch_bounds__(256, 2): cap regs at 128 to allow 2 CTAs/SM (smem 2x42KB fits).
#define APAD 24
#define WPAD 136

__global__ __launch_bounds__(256, 2) void k_gemm2(
    const __nv_bfloat16* __restrict__ Ahi, const __nv_bfloat16* __restrict__ Alo,
    const __nv_bfloat16* __restrict__ Bhi, const __nv_bfloat16* __restrict__ Blo,
    const __nv_bfloat16* __restrict__ Wrel_h, const __nv_bfloat16* __restrict__ Wrel_l,
    const __nv_bfloat16* __restrict__ Wroot_h, const __nv_bfloat16* __restrict__ Wroot_l,
    const float* __restrict__ bias,
    __nv_bfloat16* __restrict__ outh, __nv_bfloat16* __restrict__ outl,
    const float* __restrict__ eW, const float* __restrict__ erW,
    float* __restrict__ U, float* __restrict__ R,
    const float* __restrict__ rowTab, const int* __restrict__ batchIdx,
    size_t inStride, size_t outStride, size_t wStride, size_t biasStride,
    size_t projStride, int uStride,
    int do_relu, int nsteps)
{
    __shared__ __nv_bfloat16 Ah[2][128][APAD], Al[2][128][APAD];
    __shared__ __nv_bfloat16 Wh[2][16][WPAD],  Wl[2][16][WPAD];

    int ex = blockIdx.y;
    Ahi += (size_t)ex * inStride;  Alo += (size_t)ex * inStride;
    if (Bhi) { Bhi += (size_t)ex * inStride; Blo += (size_t)ex * inStride; }
    Wrel_h += (size_t)ex * wStride;  Wrel_l += (size_t)ex * wStride;
    if (Wroot_h) { Wroot_h += (size_t)ex * wStride; Wroot_l += (size_t)ex * wStride; }
    bias += (size_t)ex * biasStride;
    if (outh) { outh += (size_t)ex * outStride; outl += (size_t)ex * outStride; }
    bool project = (eW != nullptr);
    bool projR = (erW != nullptr);
    if (project) {
        eW += (size_t)ex * projStride;
        U += (size_t)ex * 4;
        if (projR) { erW += (size_t)ex * projStride; R += (size_t)ex * 4; }
    }

    int tid = threadIdx.x;
    int lane = tid & 31, wid = tid >> 5;
    int wm = wid & 3, wn = wid >> 2;
    int row0 = blockIdx.x * 128;

    float acc[2][8][4];
    #pragma unroll
    for (int i = 0; i < 2; ++i)
        #pragma unroll
        for (int j = 0; j < 8; ++j)
            #pragma unroll
            for (int k = 0; k < 4; ++k) acc[i][j][k] = 0.f;

    int ar = tid >> 1, ac = (tid & 1) * 8;
    int wk = tid >> 4, wc = (tid & 15) * 8;

    auto prefetch = [&](int kt, int st) {
        const __nv_bfloat16* Ah_src = (kt < 8) ? Ahi : Bhi;
        const __nv_bfloat16* Al_src = (kt < 8) ? Alo : Blo;
        const __nv_bfloat16* Wh_src = (kt < 8) ? Wrel_h : Wroot_h;
        const __nv_bfloat16* Wl_src = (kt < 8) ? Wrel_l : Wroot_l;
        int kk0 = (kt & 7) * 16;
        int gr = row0 + ar;
        int sz = (gr < N_NODES) ? 16 : 0;
        int grc = (gr < N_NODES) ? gr : (N_NODES - 1);
        size_t aoff = (size_t)grc * HID + kk0 + ac;
        cp16(smem_u32(&Ah[st][ar][ac]), Ah_src + aoff, sz);
        cp16(smem_u32(&Al[st][ar][ac]), Al_src + aoff, sz);
        size_t woff = (size_t)(kk0 + wk) * HID + wc;
        cp16(smem_u32(&Wh[st][wk][wc]), Wh_src + woff, 16);
        cp16(smem_u32(&Wl[st][wk][wc]), Wl_src + woff, 16);
    };

    prefetch(0, 0);
    cp_commit();

    int a_row = (lane & 15);
    int a_col = (lane >> 4) * 8;
    int b_krow = (lane & 7) + ((lane >> 3) & 1) * 8;
    int b_ncol = (lane >> 4) * 8;

    for (int kt = 0; kt < nsteps; ++kt) {
        int st = kt & 1;
        if (kt + 1 < nsteps) prefetch(kt + 1, st ^ 1);
        cp_commit();
        cp_wait1();
        __syncthreads();

        unsigned ah[2][4], al[2][4];
        #pragma unroll
        for (int mf = 0; mf < 2; ++mf) {
            int r = wm * 32 + mf * 16 + a_row;
            ldsm_x4(smem_u32(&Ah[st][r][a_col]), ah[mf][0], ah[mf][1], ah[mf][2], ah[mf][3]);
            ldsm_x4(smem_u32(&Al[st][r][a_col]), al[mf][0], al[mf][1], al[mf][2], al[mf][3]);
        }
        unsigned bh[8][2], bl[8][2];
        #pragma unroll
        for (int p = 0; p < 4; ++p) {
            int nb = wn * 64 + p * 16 + b_ncol;
            ldsm_x4_t(smem_u32(&Wh[st][b_krow][nb]),
                      bh[2*p][0], bh[2*p][1], bh[2*p+1][0], bh[2*p+1][1]);
            ldsm_x4_t(smem_u32(&Wl[st][b_krow][nb]),
                      bl[2*p][0], bl[2*p][1], bl[2*p+1][0], bl[2*p+1][1]);
        }
        #pragma unroll
        for (int mf = 0; mf < 2; ++mf)
            #pragma unroll
            for (int nf = 0; nf < 8; ++nf) {
                mma_bf16(acc[mf][nf], ah[mf], bh[nf][0], bh[nf][1]);
                mma_bf16(acc[mf][nf], ah[mf], bl[nf][0], bl[nf][1]);
                mma_bf16(acc[mf][nf], al[mf], bh[nf][0], bh[nf][1]);
            }
        __syncthreads();
    }

    float (*eWs)[4]  = (float(*)[4])((char*)&Ah[0][0][0]);
    float (*erWs)[4] = (float(*)[4])((char*)&Ah[0][0][0] + 2048);
    float (*uacc)[8] = (float(*)[8])((char*)&Ah[0][0][0] + 4096);
    if (project) {
        for (int i = tid; i < 512; i += 256) {
            ((float*)eWs)[i] = eW[i];
            if (projR) ((float*)erWs)[i] = erW[i];
        }
        for (int i = tid; i < 128 * 8; i += 256) ((float*)uacc)[i] = 0.f;
        __syncthreads();
    }

    float up[2][2][4], rp[2][2][4];
    if (project) {
        #pragma unroll
        for (int a = 0; a < 2; ++a)
            #pragma unroll
            for (int b = 0; b < 2; ++b)
                #pragma unroll
                for (int j = 0; j < 4; ++j) { up[a][b][j] = 0.f; rp[a][b][j] = 0.f; }
    }

    #pragma unroll
    for (int mf = 0; mf < 2; ++mf) {
        int rbase = wm * 32 + mf * 16 + (lane >> 2);
        int g0r = row0 + rbase, g1r = g0r + 8;
        const float* tab0 = nullptr;
        const float* tab1 = nullptr;
        if (rowTab) {
            tab0 = rowTab + (size_t)((g0r < N_NODES) ? batchIdx[g0r] : 0) * HID;
            tab1 = rowTab + (size_t)((g1r < N_NODES) ? batchIdx[g1r] : 0) * HID;
        }
        #pragma unroll
        for (int nf = 0; nf < 8; ++nf) {
            int c = wn * 64 + nf * 8 + (lane & 3) * 2;
            float b0 = __ldg(&bias[c]), b1 = __ldg(&bias[c + 1]);
            float o0 = acc[mf][nf][0] + b0, o1 = acc[mf][nf][1] + b1;
            float o2 = acc[mf][nf][2] + b0, o3 = acc[mf][nf][3] + b1;
            if (rowTab) {
                o0 += tab0[c]; o1 += tab0[c + 1];
                o2 += tab1[c]; o3 += tab1[c + 1];
            }
            if (do_relu) {
                o0 = fmaxf(o0, 0.f); o1 = fmaxf(o1, 0.f);
                o2 = fmaxf(o2, 0.f); o3 = fmaxf(o3, 0.f);
            }
            if (outh) {
                if (g0r < N_NODES) {
                    __nv_bfloat16 h0, l0, h1, l1;
                    split_bf16(o0, h0, l0); split_bf16(o1, h1, l1);
                    *(unsigned*)&outh[(size_t)g0r * HID + c] = pack2(h0, h1);
                    *(unsigned*)&outl[(size_t)g0r * HID + c] = pack2(l0, l1);
                }
                if (g1r < N_NODES) {
                    __nv_bfloat16 h2, l2, h3, l3;
                    split_bf16(o2, h2, l2); split_bf16(o3, h3, l3);
                    *(unsigned*)&outh[(size_t)g1r * HID + c] = pack2(h2, h3);
                    *(unsigned*)&outl[(size_t)g1r * HID + c] = pack2(l2, l3);
                }
            }
            if (project) {
                #pragma unroll
                for (int j = 0; j < 4; ++j) {
                    up[mf][0][j] += o0 * eWs[c][j] + o1 * eWs[c + 1][j];
                    up[mf][1][j] += o2 * eWs[c][j] + o3 * eWs[c + 1][j];
                    if (projR) {
                        rp[mf][0][j] += o0 * erWs[c][j] + o1 * erWs[c + 1][j];
                        rp[mf][1][j] += o2 * erWs[c][j] + o3 * erWs[c + 1][j];
                    }
                }
            }
        }
    }

    if (project) {
        #pragma unroll
        for (int a = 0; a < 2; ++a)
            #pragma unroll
            for (int b = 0; b < 2; ++b)
                #pragma unroll
                for (int j = 0; j < 4; ++j) {
                    up[a][b][j] += __shfl_xor_sync(0xffffffffu, up[a][b][j], 1);
                    up[a][b][j] += __shfl_xor_sync(0xffffffffu, up[a][b][j], 2);
                    if (projR) {
                        rp[a][b][j] += __shfl_xor_sync(0xffffffffu, rp[a][b][j], 1);
                        rp[a][b][j] += __shfl_xor_sync(0xffffffffu, rp[a][b][j], 2);
                    }
                }
        if ((lane & 3) == 0) {
            #pragma unroll
            for (int a = 0; a < 2; ++a)
                #pragma unroll
                for (int b = 0; b < 2; ++b) {
                    int r = wm * 32 + a * 16 + b * 8 + (lane >> 2);
                    #pragma unroll
                    for (int j = 0; j < 4; ++j) {
                        atomicAdd(&uacc[r][j], up[a][b][j]);
                        if (projR) atomicAdd(&uacc[r][4 + j], rp[a][b][j]);
                    }
                }
        }
        __syncthreads();
        if (tid < 128) {
            int g = row0 + tid;
            if (g < N_NODES) {
                *(float4*)&U[(size_t)g * uStride] = make_float4(uacc[tid][0], uacc[tid][1],
                                                                uacc[tid][2], uacc[tid][3]);
                if (projR)
                    *(float4*)&R[(size_t)g * uStride] = make_float4(uacc[tid][4], uacc[tid][5],
                                                                    uacc[tid][6], uacc[tid][7]);
            }
        }
    }
}

// ---------------- weight pre-split (mat range [m0,m1)) ----------------
__global__ void k_convw(const float* __restrict__ sRelW, const float* __restrict__ sRootW,
                        const float* __restrict__ mRelW, const float* __restrict__ mRootW,
                        const float* __restrict__ encW2, const float* __restrict__ rtW1,
                        __nv_bfloat16* __restrict__ wh, __nv_bfloat16* __restrict__ wl,
                        int m0, int m1) {
    int i = blockIdx.x * blockDim.x + threadIdx.x;
    int n = (m1 - m0) * HID * HID;
    if (i >= n) return;
    int mat = m0 + i / (HID * HID), off = i % (HID * HID);
    float v;
    if (mat == 16) v = encW2[off];
    else if (mat == 17) v = rtW1[off];
    else {
        const float* srcs[4] = {sRelW, sRootW, mRelW, mRootW};
        v = srcs[mat >> 2][(size_t)(mat & 3) * HID * HID + off];
    }
    __nv_bfloat16 h, l;
    split_bf16(v, h, l);
    wh[(size_t)mat * HID * HID + off] = h;
    wl[(size_t)mat * HID * HID + off] = l;
}

// ---------------- encoder layer 1 ----------------
__global__ void k_enc1(const float* __restrict__ x,
                       const float* __restrict__ W1, const float* __restrict__ b1,
                       __nv_bfloat16* __restrict__ oh, __nv_bfloat16* __restrict__ ol) {
    __shared__ float xs[8][8];
    int n0 = blockIdx.x * 8;
    int t = threadIdx.x;
    if (t < 48) {
        int j = t / 6, f = t % 6;
        int node = n0 + j;
        xs[j][f] = (node < N_NODES) ? x[(size_t)node * 16 + 4 + f] : 0.f;
    }
    __syncthreads();
    float bb1 = b1[t];
    float w[6];
    #pragma unroll
    for (int f = 0; f < 6; ++f) w[f] = __ldg(&W1[f * HID + t]);
    #pragma unroll
    for (int j = 0; j < 8; ++j) {
        int node = n0 + j;
        if (node >= N_NODES) break;
        float acc = bb1;
        #pragma unroll
        for (int f = 0; f < 6; ++f) acc += xs[j][f] * w[f];
        acc = fmaxf(acc, 0.f);
        __nv_bfloat16 hi, lo;
        split_bf16(acc, hi, lo);
        oh[(size_t)node * HID + t] = hi;
        ol[(size_t)node * HID + t] = lo;
    }
}

// ---------------- CSR build ----------------
__global__ void k_count(const int* __restrict__ dst, int* __restrict__ cnt) {
    int e = blockIdx.x * blockDim.x + threadIdx.x;
    if (e < N_EDGES) atomicAdd(&cnt[dst[e]], 1);
}
__global__ void k_scan1(const int* __restrict__ cnt, int* __restrict__ rs,
                        int* __restrict__ bsum) {
    __shared__ int s[256];
    int i = blockIdx.x * 256 + threadIdx.x;
    int v = (i < N_NODES) ? cnt[i] : 0;
    s[threadIdx.x] = v;
    __syncthreads();
    #pragma unroll
    for (int o = 1; o < 256; o <<= 1) {
        int t = (threadIdx.x >= o) ? s[threadIdx.x - o] : 0;
        __syncthreads();
        s[threadIdx.x] += t;
        __syncthreads();
    }
    if (i < N_NODES) rs[i] = s[threadIdx.x] - v;
    if (threadIdx.x == 255) bsum[blockIdx.x] = s[255];
}
__global__ void k_scan2(int* __restrict__ bsum) {
    __shared__ int s[512];
    int v = (threadIdx.x < SCAN_BLOCKS) ? bsum[threadIdx.x] : 0;
    s[threadIdx.x] = v;
    __syncthreads();
    #pragma unroll
    for (int o = 1; o < 512; o <<= 1) {
        int t = (threadIdx.x >= o) ? s[threadIdx.x - o] : 0;
        __syncthreads();
        s[threadIdx.x] += t;
        __syncthreads();
    }
    if (threadIdx.x < SCAN_BLOCKS) bsum[threadIdx.x] = s[threadIdx.x] - v;
}
__global__ void k_scan3(int* __restrict__ rs, const int* __restrict__ bsum) {
    int i = blockIdx.x * 256 + threadIdx.x;
    if (i < N_NODES) rs[i] += bsum[blockIdx.x];
}
__global__ void k_place(const int* __restrict__ src, const int* __restrict__ dst,
                        const int* __restrict__ rs, int* __restrict__ cnt2,
                        int* __restrict__ csr) {
    int e = blockIdx.x * blockDim.x + threadIdx.x;
    if (e >= N_EDGES) return;
    int d = dst[e];
    int pos = rs[d] + atomicAdd(&cnt2[d], 1);
    csr[pos] = src[e];
}

// ---------------- CSR gather: hi/lo lane split + 2-edge unroll ----------------
__global__ void k_gatherb(const __nv_bfloat16* __restrict__ fh,
                          const __nv_bfloat16* __restrict__ fl,
                          const int* __restrict__ rs, const int* __restrict__ cnt,
                          const int* __restrict__ csr,
                          __nv_bfloat16* __restrict__ oh, __nv_bfloat16* __restrict__ ol,
                          size_t exStride) {
    size_t off0 = (size_t)blockIdx.y * exStride;
    fh += off0; fl += off0; oh += off0; ol += off0;
    int node = (blockIdx.x * blockDim.x + threadIdx.x) >> 5;
    int lane = threadIdx.x & 31;
    if (node >= N_NODES) return;
    int start = rs[node], deg = cnt[node];
    const __nv_bfloat16* base = (lane < 16) ? fh : fl;
    int c8 = (lane & 15) * 8;
    float a[8] = {0.f, 0.f, 0.f, 0.f, 0.f, 0.f, 0.f, 0.f};
    int e = 0;
    for (; e + 1 < deg; e += 2) {
        int sid0 = __ldg(&csr[start + e]);
        int sid1 = __ldg(&csr[start + e + 1]);
        uint4 v0 = *(const uint4*)&base[(size_t)sid0 * HID + c8];
        uint4 v1 = *(const uint4*)&base[(size_t)sid1 * HID + c8];
        const __nv_bfloat162* p0 = (const __nv_bfloat162*)&v0;
        const __nv_bfloat162* p1 = (const __nv_bfloat162*)&v1;
        #pragma unroll
        for (int q = 0; q < 4; ++q) {
            a[2 * q]     += __bfloat162float(p0[q].x);
            a[2 * q + 1] += __bfloat162float(p0[q].y);
        }
        #pragma unroll
        for (int q = 0; q < 4; ++q) {
            a[2 * q]     += __bfloat162float(p1[q].x);
            a[2 * q + 1] += __bfloat162float(p1[q].y);
        }
    }
    if (e < deg) {
        int sid = __ldg(&csr[start + e]);
        uint4 v = *(const uint4*)&base[(size_t)sid * HID + c8];
        const __nv_bfloat162* pp = (const __nv_bfloat162*)&v;
        #pragma unroll
        for (int q = 0; q < 4; ++q) {
            a[2 * q]     += __bfloat162float(pp[q].x);
            a[2 * q + 1] += __bfloat162float(pp[q].y);
        }
    }
    #pragma unroll
    for (int q = 0; q < 8; ++q)
        a[q] += __shfl_down_sync(0xffffffffu, a[q], 16);
    if (lane < 16) {
        unsigned hs[4], ls[4];
        #pragma unroll
        for (int q = 0; q < 4; ++q) {
            __nv_bfloat16 h0, l0, h1, l1;
            split_bf16(a[2 * q], h0, l0);
            split_bf16(a[2 * q + 1], h1, l1);
            hs[q] = pack2(h0, h1);
            ls[q] = pack2(l0, l1);
        }
        size_t o = (size_t)node * HID + c8;
        *(uint4*)&oh[o] = make_uint4(hs[0], hs[1], hs[2], hs[3]);
        *(uint4*)&ol[o] = make_uint4(ls[0], ls[1], ls[2], ls[3]);
    }
}

// ---------------- graph stats ----------------
__global__ void k_node_count(const int* __restrict__ batch, float* __restrict__ ncnt) {
    int g = threadIdx.x;
    if (g >= NUM_GRAPHS) return;
    int lo = 0, hi = N_NODES;
    while (lo < hi) { int m = (lo + hi) >> 1; if (batch[m] < g) lo = m + 1; else hi = m; }
    int a = lo;
    lo = 0; hi = N_NODES;
    while (lo < hi) { int m = (lo + hi) >> 1; if (batch[m] < g + 1) lo = m + 1; else hi = m; }
    ncnt[g] = (float)(lo - a);
}
__global__ void k_edge_count(const int* __restrict__ src, const int* __restrict__ batch,
                             float* __restrict__ ecnt) {
    __shared__ float sc[NUM_GRAPHS];
    int t = threadIdx.x;
    if (t < NUM_GRAPHS) sc[t] = 0.f;
    __syncthreads();
    for (int e = blockIdx.x * blockDim.x + t; e < N_EDGES; e += gridDim.x * blockDim.x)
        atomicAdd(&sc[batch[src[e]]], 1.f);
    __syncthreads();
    if (t < NUM_GRAPHS) atomicAdd(&ecnt[t], sc[t]);
}
__global__ void k_stats(const float* __restrict__ ncnt, const float* __restrict__ ecnt,
                        float* __restrict__ sf, float* __restrict__ lnn) {
    __shared__ float nn[64], ee[64], dd[64], ll[64];
    __shared__ float mean[3], istd[3], lmin, lrange;
    int g = threadIdx.x;
    float n = fmaxf(ncnt[g], 1.f);
    float e = ecnt[g];
    float d = e / fmaxf(n * (n - 1.f), 1.f);
    float lg = logf(n);
    nn[g] = n; ee[g] = e; dd[g] = d; ll[g] = lg;
    __syncthreads();
    if (g == 0) {
        double s0 = 0, s1 = 0, s2 = 0;
        float mn = ll[0], mx = ll[0];
        for (int i = 0; i < 64; ++i) {
            s0 += nn[i]; s1 += ee[i]; s2 += dd[i];
            mn = fminf(mn, ll[i]); mx = fmaxf(mx, ll[i]);
        }
        double m0 = s0 / 64, m1 = s1 / 64, m2 = s2 / 64;
        double v0 = 0, v1 = 0, v2 = 0;
        for (int i = 0; i < 64; ++i) {
            double a = nn[i] - m0, b = ee[i] - m1, c = dd[i] - m2;
            v0 += a * a; v1 += b * b; v2 += c * c;
        }
        mean[0] = (float)m0; mean[1] = (float)m1; mean[2] = (float)m2;
        istd[0] = 1.f / ((float)sqrt(v0 / 64) + 1e-6f);
        istd[1] = 1.f / ((float)sqrt(v1 / 64) + 1e-6f);
        istd[2] = 1.f / ((float)sqrt(v2 / 64) + 1e-6f);
        lmin = mn; lrange = mx - mn + 1e-6f;
    }
    __syncthreads();
    sf[g * 3 + 0] = (nn[g] - mean[0]) * istd[0];
    sf[g * 3 + 1] = (ee[g] - mean[1]) * istd[1];
    sf[g * 3 + 2] = (dd[g] - mean[2]) * istd[2];
    lnn[g] = (ll[g] - lmin) / lrange;
}
__global__ void k_sfproj(const float* __restrict__ sf, const float* __restrict__ rtW1,
                         float* __restrict__ C) {
    int g = blockIdx.x, c = threadIdx.x;
    C[g * HID + c] = sf[g * 3 + 0] * rtW1[128 * HID + c]
                   + sf[g * 3 + 1] * rtW1[129 * HID + c]
                   + sf[g * 3 + 2] * rtW1[130 * HID + c];
}

// ---------------- gating ----------------
__global__ void k_gating(const float* __restrict__ logits, const int* __restrict__ batch,
                         const float* __restrict__ lnn, const float* __restrict__ centers,
                         const float* __restrict__ b2, float* __restrict__ w) {
    int i = blockIdx.x * blockDim.x + threadIdx.x;
    if (i >= N_NODES) return;
    float4 lg = *(const float4*)&logits[(size_t)i * 4];
    float ln = lnn[batch[i]];
    float l[4];
    float c0 = centers[0], c1 = centers[1], c2 = centers[2], c3 = centers[3];
    float d0 = ln - c0, d1 = ln - c1, d2 = ln - c2, d3 = ln - c3;
    l[0] = (1.f - PRIOR_W) * (lg.x + b2[0]) - PRIOR_W * d0 * d0;
    l[1] = (1.f - PRIOR_W) * (lg.y + b2[1]) - PRIOR_W * d1 * d1;
    l[2] = (1.f - PRIOR_W) * (lg.z + b2[2]) - PRIOR_W * d2 * d2;
    l[3] = (1.f - PRIOR_W) * (lg.w + b2[3]) - PRIOR_W * d3 * d3;
    float m = fmaxf(fmaxf(l[0], l[1]), fmaxf(l[2], l[3]));
    float p[4], s = 0.f;
    #pragma unroll
    for (int k = 0; k < 4; ++k) { p[k] = expf(l[k] - m); s += p[k]; }
    #pragma unroll
    for (int k = 0; k < 4; ++k) p[k] /= s;
    int i1 = 0;
    for (int k = 1; k < 4; ++k) if (p[k] > p[i1]) i1 = k;
    int i2 = -1;
    for (int k = 0; k < 4; ++k) { if (k == i1) continue; if (i2 < 0 || p[k] > p[i2]) i2 = k; }
    float inv = 1.f / (p[i1] + p[i2] + 1e-8f);
    float ww[4] = {0.f, 0.f, 0.f, 0.f};
    ww[i1] = p[i1] * inv; ww[i2] = p[i2] * inv;
    *(float4*)&w[(size_t)i * 4] = make_float4(ww[0], ww[1], ww[2], ww[3]);
}

// ---------------- fused finale ----------------
__global__ void k_final_all(const float* __restrict__ U, const float* __restrict__ R,
                            const float* __restrict__ eRelB, const float* __restrict__ w,
                            const int* __restrict__ rs, const int* __restrict__ cnt,
                            const int* __restrict__ csr, float* __restrict__ out) {
    int node = (blockIdx.x * blockDim.x + threadIdx.x) >> 5;
    int lane = threadIdx.x & 31;
    if (node >= N_NODES) return;
    int start = rs[node], deg = cnt[node];
    int comp = lane & 15;
    float acc = 0.f;
    for (int e2 = lane >> 4; e2 < deg; e2 += 2) {
        int sid = __ldg(&csr[start + e2]);
        acc += U[(size_t)sid * 16 + comp];
    }
    acc += __shfl_down_sync(0xffffffffu, acc, 16);
    float val = 0.f;
    if (lane < 16) {
        int e = comp >> 2;
        val = (acc + __ldg(&eRelB[comp]) + R[(size_t)node * 16 + comp])
              * w[(size_t)node * 4 + e];
    }
    val += __shfl_down_sync(0xffffffffu, val, 8);
    val += __shfl_down_sync(0xffffffffu, val, 4);
    if (lane < 4) out[(size_t)node * 4 + lane] = val;
}

// ---------------- host ----------------
extern "C" void kernel_launch(void* const* d_in, const int* in_sizes, int n_in,
                              void* d_out, int out_size) {
    const float* x       = (const float*)d_in[0];
    const int*   ei      = (const int*)d_in[1];
    const int*   src     = ei;
    const int*   dst     = ei + N_EDGES;
    const int*   batch   = (const int*)d_in[2];
    const float* encW1   = (const float*)d_in[3];
    const float* encb1   = (const float*)d_in[4];
    const float* encW2   = (const float*)d_in[5];
    const float* encb2   = (const float*)d_in[6];
    const float* rtW1    = (const float*)d_in[7];
    const float* rtb1    = (const float*)d_in[8];
    const float* rtW2    = (const float*)d_in[9];
    const float* rtb2    = (const float*)d_in[10];
    const float* centers = (const float*)d_in[11];
    const float* sRelW   = (const float*)d_in[12];
    const float* sRelB   = (const float*)d_in[13];
    const float* sRootW  = (const float*)d_in[14];
    const float* mRelW   = (const float*)d_in[15];
    const float* mRelB   = (const float*)d_in[16];
    const float* mRootW  = (const float*)d_in[17];
    const float* eRelW   = (const float*)d_in[18];
    const float* eRelB   = (const float*)d_in[19];
    const float* eRootW  = (const float*)d_in[20];
    float* out = (float*)d_out;

    void* p;
    cudaGetSymbolAddress(&p, g_U);    float* U    = (float*)p;
    cudaGetSymbolAddress(&p, g_R);    float* R    = (float*)p;
    cudaGetSymbolAddress(&p, g_RT);   float* RT   = (float*)p;
    cudaGetSymbolAddress(&p, g_GW);   float* GW   = (float*)p;
    cudaGetSymbolAddress(&p, g_C);    float* C    = (float*)p;
    cudaGetSymbolAddress(&p, g_NCNT); float* NCNT = (float*)p;
    cudaGetSymbolAddress(&p, g_ECNT); float* ECNT = (float*)p;
    cudaGetSymbolAddress(&p, g_SF);   float* SF   = (float*)p;
    cudaGetSymbolAddress(&p, g_LNN);  float* LNN  = (float*)p;
    cudaGetSymbolAddress(&p, g_Hh);   __nv_bfloat16* Hh   = (__nv_bfloat16*)p;
    cudaGetSymbolAddress(&p, g_Hl);   __nv_bfloat16* Hl   = (__nv_bfloat16*)p;
    cudaGetSymbolAddress(&p, g_Z1h);  __nv_bfloat16* Z1h  = (__nv_bfloat16*)p;
    cudaGetSymbolAddress(&p, g_Z1l);  __nv_bfloat16* Z1l  = (__nv_bfloat16*)p;
    cudaGetSymbolAddress(&p, g_AGHh); __nv_bfloat16* AGHh = (__nv_bfloat16*)p;
    cudaGetSymbolAddress(&p, g_AGHl); __nv_bfloat16* AGHl = (__nv_bfloat16*)p;
    cudaGetSymbolAddress(&p, g_AGZh); __nv_bfloat16* AGZh = (__nv_bfloat16*)p;
    cudaGetSymbolAddress(&p, g_AGZl); __nv_bfloat16* AGZl = (__nv_bfloat16*)p;
    cudaGetSymbolAddress(&p, g_Wh);   __nv_bfloat16* Wh   = (__nv_bfloat16*)p;
    cudaGetSymbolAddress(&p, g_Wl);   __nv_bfloat16* Wl   = (__nv_bfloat16*)p;
    cudaGetSymbolAddress(&p, g_cnt);  int* CNT  = (int*)p;
    cudaGetSymbolAddress(&p, g_cnt2); int* CNT2 = (int*)p;
    cudaGetSymbolAddress(&p, g_rs);   int* RS   = (int*)p;
    cudaGetSymbolAddress(&p, g_bsum); int* BSUM = (int*)p;
    cudaGetSymbolAddress(&p, g_csr);  int* CSR  = (int*)p;

    const size_t MS = (size_t)HID * HID;
    int gemm_blocks = (N_NODES + 127) / 128;
    int gather_blocks = (N_NODES * 32 + 255) / 256;

    cudaStream_t s[N_EXP];
    for (int i = 0; i < N_EXP; ++i) cudaStreamCreateWithFlags(&s[i], cudaStreamNonBlocking);
    cudaEvent_t evRoot, evCSR, evH, evGW, evAGH, evWB, evE[N_EXP];
    cudaEventCreateWithFlags(&evRoot, cudaEventDisableTiming);
    cudaEventCreateWithFlags(&evCSR, cudaEventDisableTiming);
    cudaEventCreateWithFlags(&evH, cudaEventDisableTiming);
    cudaEventCreateWithFlags(&evGW, cudaEventDisableTiming);
    cudaEventCreateWithFlags(&evAGH, cudaEventDisableTiming);
    cudaEventCreateWithFlags(&evWB, cudaEventDisableTiming);
    for (int i = 0; i < N_EXP; ++i) cudaEventCreateWithFlags(&evE[i], cudaEventDisableTiming);

    cudaEventRecord(evRoot, 0);

    // ---- side stream s[0]: CSR build ----
    cudaStreamWaitEvent(s[0], evRoot, 0);
    cudaMemsetAsync(CNT, 0, N_NODES * sizeof(int), s[0]);
    cudaMemsetAsync(CNT2, 0, N_NODES * sizeof(int), s[0]);
    k_count<<<(N_EDGES + 255) / 256, 256, 0, s[0]>>>(dst, CNT);
    k_scan1<<<SCAN_BLOCKS, 256, 0, s[0]>>>(CNT, RS, BSUM);
    k_scan2<<<1, 512, 0, s[0]>>>(BSUM);
    k_scan3<<<SCAN_BLOCKS, 256, 0, s[0]>>>(RS, BSUM);
    k_place<<<(N_EDGES + 255) / 256, 256, 0, s[0]>>>(src, dst, RS, CNT2, CSR);
    cudaEventRecord(evCSR, s[0]);

    // ---- side stream s[1]: stats, later router+gating ----
    cudaStreamWaitEvent(s[1], evRoot, 0);
    k_node_count<<<1, 64, 0, s[1]>>>(batch, NCNT);
    cudaMemsetAsync(ECNT, 0, NUM_GRAPHS * sizeof(float), s[1]);
    k_edge_count<<<1024, 256, 0, s[1]>>>(src, batch, ECNT);
    k_stats<<<1, 64, 0, s[1]>>>(NCNT, ECNT, SF, LNN);
    k_sfproj<<<NUM_GRAPHS, HID, 0, s[1]>>>(SF, rtW1, C);

    // ---- side stream s[2]: expert weight pre-split (mats 0..15) ----
    cudaStreamWaitEvent(s[2], evRoot, 0);
    k_convw<<<(16 * HID * HID + 255) / 256, 256, 0, s[2]>>>(
        sRelW, sRootW, mRelW, mRootW, encW2, rtW1, Wh, Wl, 0, 16);
    cudaEventRecord(evWB, s[2]);

    // ---- default (critical path): enc/router weights, encoder ----
    k_convw<<<(2 * HID * HID + 255) / 256, 256>>>(
        sRelW, sRootW, mRelW, mRootW, encW2, rtW1, Wh, Wl, 16, 18);
    k_enc1<<<(N_NODES + 7) / 8, 128>>>(x, encW1, encb1, Z1h, Z1l);  // reuse Z1[0] as h1
    k_gemm2<<<gemm_blocks, 256>>>(Z1h, Z1l, nullptr, nullptr,
        Wh + 16 * MS, Wl + 16 * MS, nullptr, nullptr,
        encb2, Hh, Hl, nullptr, nullptr, nullptr, nullptr, nullptr, nullptr,
        0, 0, 0, 0, 0, 4, 0, 8);
    cudaEventRecord(evH, 0);

    // router+gating on s[1] (dedicated RT buffer -> no aliasing with expert U)
    cudaStreamWaitEvent(s[1], evH, 0);
    k_gemm2<<<gemm_blocks, 256, 0, s[1]>>>(Hh, Hl, nullptr, nullptr,
        Wh + 17 * MS, Wl + 17 * MS, nullptr, nullptr,
        rtb1, nullptr, nullptr, rtW2, nullptr, RT, nullptr, C, batch,
        0, 0, 0, 0, 0, 4, 1, 8);
    k_gating<<<(N_NODES + 255) / 256, 256, 0, s[1]>>>(RT, batch, LNN, centers, rtb2, GW);
    cudaEventRecord(evGW, s[1]);

    // ---- default: join CSR, shared start aggregation ----
    cudaStreamWaitEvent(0, evCSR, 0);
    k_gatherb<<<gather_blocks, 256>>>(Hh, Hl, RS, CNT, CSR, AGHh, AGHl, 0);
    cudaEventRecord(evAGH, 0);

    // ---- per-expert pipelines (wait only AGH + weights; router fully decoupled) ----
    for (int e = 0; e < N_EXP; ++e) {
        cudaStreamWaitEvent(s[e], evAGH, 0);
        cudaStreamWaitEvent(s[e], evWB, 0);
        k_gemm2<<<gemm_blocks, 256, 0, s[e]>>>(AGHh, AGHl, Hh, Hl,
            Wh + (size_t)e * MS, Wl + (size_t)e * MS,
            Wh + (size_t)(4 + e) * MS, Wl + (size_t)(4 + e) * MS,
            sRelB + (size_t)e * HID, Z1h + (size_t)e * NH, Z1l + (size_t)e * NH,
            nullptr, nullptr, nullptr, nullptr, nullptr, nullptr,
            0, 0, 0, 0, 0, 4, 1, 16);
        k_gatherb<<<gather_blocks, 256, 0, s[e]>>>(Z1h + (size_t)e * NH, Z1l + (size_t)e * NH,
            RS, CNT, CSR, AGZh + (size_t)e * NH, AGZl + (size_t)e * NH, 0);
        k_gemm2<<<gemm_blocks, 256, 0, s[e]>>>(AGZh + (size_t)e * NH, AGZl + (size_t)e * NH,
            Z1h + (size_t)e * NH, Z1l + (size_t)e * NH,
            Wh + (size_t)(8 + e) * MS, Wl + (size_t)(8 + e) * MS,
            Wh + (size_t)(12 + e) * MS, Wl + (size_t)(12 + e) * MS,
            mRelB + (size_t)e * HID, nullptr, nullptr,
            eRelW + (size_t)e * HID * OUTD, eRootW + (size_t)e * HID * OUTD,
            U + e * 4, R + e * 4, nullptr, nullptr,
            0, 0, 0, 0, 0, 16, 1, 16);
        cudaEventRecord(evE[e], s[e]);
    }
    for (int e = 0; e < N_EXP; ++e) cudaStreamWaitEvent(0, evE[e], 0);
    cudaStreamWaitEvent(0, evGW, 0);

    // finale on default stream
    k_final_all<<<gather_blocks, 256>>>(U, R, eRelB, GW, RS, CNT, CSR, out);

    for (int i = 0; i < N_EXP; ++i) cudaStreamDestroy(s[i]);
    cudaEventDestroy(evRoot); cudaEventDestroy(evCSR); cudaEventDestroy(evH);
    cudaEventDestroy(evGW); cudaEventDestroy(evAGH); cudaEventDestroy(evWB);
    for (int i = 0; i < N_EXP; ++i) cudaEventDestroy(evE[i]);
}